// round 11
// baseline (speedup 1.0000x reference)
#include <cuda_runtime.h>
#include <cuda_fp16.h>
#include <cstdint>
#include <cstddef>

#define Bsz  64
#define Tlen 4096
#define DIN  64
#define DEMB 24
#define Hdim 128

// Scratch (static device globals — no allocation in kernel_launch)
__device__ float  g_e[(size_t)Bsz * Tlen * DEMB];              // 25 MB
__device__ __half g_u16[(size_t)Bsz * Tlen * 4 * Hdim];        // 256 MB, layout [row][j*4+gate]

__device__ __forceinline__ float tanhfast(float x) {
    float y;
    asm("tanh.approx.f32 %0, %1;" : "=f"(y) : "f"(x));
    return y;
}
__device__ __forceinline__ float fsigmoid(float z) {
    return fmaf(0.5f, tanhfast(0.5f * z), 0.5f);
}
__device__ __forceinline__ uint32_t smem_u32(const void* p) {
    uint32_t a;
    asm("{ .reg .u64 t; cvta.to.shared.u64 t, %1; cvt.u32.u64 %0, t; }"
        : "=r"(a) : "l"(p));
    return a;
}

// ---------------------------------------------------------------------------
// K1: e[r][j] = sigmoid(x[r,:] @ W_emb[:,j] + b_emb[j])   (unchanged)
// ---------------------------------------------------------------------------
__global__ void __launch_bounds__(256) emb_kernel(
    const float* __restrict__ x,
    const float* __restrict__ W_emb,
    const float* __restrict__ b_emb)
{
    __shared__ float ws[DIN * DEMB];
    __shared__ float bs[DEMB];
    for (int i = threadIdx.x; i < DIN * DEMB; i += 256) ws[i] = W_emb[i];
    if (threadIdx.x < DEMB) bs[threadIdx.x] = b_emb[threadIdx.x];
    __syncthreads();

    size_t r = (size_t)blockIdx.x * 256 + threadIdx.x;
    const float* xr = x + r * DIN;

    float acc[DEMB];
#pragma unroll
    for (int j = 0; j < DEMB; j++) acc[j] = bs[j];

#pragma unroll 1
    for (int d4 = 0; d4 < DIN; d4 += 4) {
        float4 xq = *reinterpret_cast<const float4*>(xr + d4);
        float xa[4] = { xq.x, xq.y, xq.z, xq.w };
#pragma unroll
        for (int q = 0; q < 4; q++) {
            const float4* wp = reinterpret_cast<const float4*>(ws + (d4 + q) * DEMB);
#pragma unroll
            for (int m = 0; m < 6; m++) {
                float4 wv = wp[m];
                acc[m * 4 + 0] = fmaf(xa[q], wv.x, acc[m * 4 + 0]);
                acc[m * 4 + 1] = fmaf(xa[q], wv.y, acc[m * 4 + 1]);
                acc[m * 4 + 2] = fmaf(xa[q], wv.z, acc[m * 4 + 2]);
                acc[m * 4 + 3] = fmaf(xa[q], wv.w, acc[m * 4 + 3]);
            }
        }
    }

    float* er = g_e + r * DEMB;
#pragma unroll
    for (int j = 0; j < DEMB; j++) er[j] = fsigmoid(acc[j]);
}

// ---------------------------------------------------------------------------
// K2: u[r][j*4+g] = e[r,:] @ Wg[0:24, j] + bg[j]  (fp16 out)  (unchanged)
// ---------------------------------------------------------------------------
__global__ void __launch_bounds__(256) ugemm_kernel(
    const float* __restrict__ Wf, const float* __restrict__ bf,
    const float* __restrict__ Wi, const float* __restrict__ bi,
    const float* __restrict__ Wc, const float* __restrict__ bc,
    const float* __restrict__ Wo, const float* __restrict__ bo)
{
    __shared__ float es[32][DEMB];
    size_t r0 = (size_t)blockIdx.x * 32;
    for (int i = threadIdx.x; i < 32 * DEMB; i += 256)
        es[i / DEMB][i % DEMB] = g_e[r0 * DEMB + i];
    __syncthreads();

    int tid = threadIdx.x;
    int j   = tid & 127;

    float wreg[4][DEMB];
#pragma unroll
    for (int d = 0; d < DEMB; d++) {
        wreg[0][d] = Wf[d * Hdim + j];
        wreg[1][d] = Wi[d * Hdim + j];
        wreg[2][d] = Wc[d * Hdim + j];
        wreg[3][d] = Wo[d * Hdim + j];
    }
    float bias[4] = { bf[j], bi[j], bc[j], bo[j] };

    int rbase = (tid >> 7) * 16;
#pragma unroll 1
    for (int rr = 0; rr < 16; rr++) {
        int row = rbase + rr;
        float a0 = bias[0], a1 = bias[1], a2 = bias[2], a3 = bias[3];
#pragma unroll
        for (int d = 0; d < DEMB; d++) {
            float ev = es[row][d];
            a0 = fmaf(ev, wreg[0][d], a0);
            a1 = fmaf(ev, wreg[1][d], a1);
            a2 = fmaf(ev, wreg[2][d], a2);
            a3 = fmaf(ev, wreg[3][d], a3);
        }
        __half2 lo = __floats2half2_rn(a0, a1);
        __half2 hi = __floats2half2_rn(a2, a3);
        uint2 v;
        v.x = *reinterpret_cast<uint32_t*>(&lo);
        v.y = *reinterpret_cast<uint32_t*>(&hi);
        *reinterpret_cast<uint2*>(g_u16 + ((r0 + row) * 512 + j * 4)) = v;
    }
}

// ---------------------------------------------------------------------------
// K3: clustered scan. 128 CTAs (2-CTA cluster per batch), 512 threads.
//     CTA rank r owns units [64r, 64r+64). Warp w owns 4 units; lane l:
//       khalf = l>>4 (k-range half), unit = 64r + 4w + ((l&15)>>2), gate = l&3.
//     GEMV: 32 HFMA2/thread over own k-half; halves combined via shfl_xor(16).
//     h (fp16, full 128) double-buffered in BOTH CTAs' smem; each CTA pushes
//     its 64 h values to the peer via st.shared::cluster (128 B/step).
//     Sync: __syncthreads -> tid0 fence.acq_rel.cluster + relaxed remote flag
//     store -> all threads relaxed-poll own flag + acquire fence.
// ---------------------------------------------------------------------------
__global__ void __launch_bounds__(512, 1) __cluster_dims__(2, 1, 1)
scan_kernel(
    const float* __restrict__ Wf, const float* __restrict__ Wi,
    const float* __restrict__ Wc, const float* __restrict__ Wo,
    const float* __restrict__ W_out, const float* __restrict__ b_out,
    float* __restrict__ out)
{
    const int b    = blockIdx.x >> 1;        // batch = cluster id
    uint32_t rank;
    asm("mov.u32 %0, %%cluster_ctarank;" : "=r"(rank));
    const int t     = threadIdx.x;
    const int l     = t & 31;
    const int w5    = t >> 5;                // warp 0..15
    const int khalf = l >> 4;                // 0/1: k in [64*khalf, 64*khalf+64)
    const int l15   = l & 15;
    const int j     = (int)rank * 64 + (w5 << 2) + (l15 >> 2);  // unit 0..127
    const int g     = l & 3;                 // gate: 0=f 1=i 2=c(g) 3=o
    const int qbase = l & ~3;
    const unsigned FULL = 0xFFFFFFFFu;

    const float* Wg = g == 0 ? Wf : g == 1 ? Wi : g == 2 ? Wc : Wo;

    // 32 half2 recurrent weights: rows 24 + 64*khalf + [0,64), column j
    __half2 wr[32];
#pragma unroll
    for (int k = 0; k < 32; k++) {
        int row = DEMB + 64 * khalf + 2 * k;
        wr[k] = __floats2half2_rn(Wg[row * Hdim + j], Wg[(row + 1) * Hdim + j]);
    }

    const float sc = (g == 2) ? 1.f : 0.5f;
    const float mm = (g == 2) ? 1.f : 0.5f;
    const float aa = (g == 2) ? 0.f : 0.5f;

    __shared__ __align__(16) __half   hbuf[2][Hdim];
    __shared__ __align__(16) float    hfin[Hdim];
    __shared__ __align__(16) unsigned flag;

    if (t < Hdim) hbuf[0][t] = __float2half_rn(0.f);
    if (t == 0)   flag = 0;
    __syncthreads();
    // publish inits cluster-wide before any remote traffic
    asm volatile("barrier.cluster.arrive.aligned;" ::: "memory");
    asm volatile("barrier.cluster.wait.aligned;"   ::: "memory");

    // peer shared-memory addresses (rank^1)
    const uint32_t my_hbuf = smem_u32(&hbuf[0][0]);
    const uint32_t my_flag = smem_u32(&flag);
    const uint32_t my_hfin = smem_u32(&hfin[0]);
    const uint32_t peer = rank ^ 1u;
    uint32_t peer_hbuf, peer_flag, peer_hfin;
    asm("mapa.shared::cluster.u32 %0, %1, %2;" : "=r"(peer_hbuf) : "r"(my_hbuf), "r"(peer));
    asm("mapa.shared::cluster.u32 %0, %1, %2;" : "=r"(peer_flag) : "r"(my_flag), "r"(peer));
    asm("mapa.shared::cluster.u32 %0, %1, %2;" : "=r"(peer_hfin) : "r"(my_hfin), "r"(peer));

    const bool writer = ((l & 0x13) == 0);   // khalf==0 && gate==0 (lanes 0,4,8,12)
    float c = 0.f;

    // u column for this thread: rank*256 + w5*16 + l15  (== j*4+g)
    const __half* up = g_u16 + ((size_t)b * Tlen) * 512
                     + (size_t)((int)rank * 256 + w5 * 16 + l15);
    float  u_cur = __half2float(up[0]);
    __half u_n1  = up[512];
    __half u_n2  = up[1024];

    const __half2 z2 = __floats2half2_rn(0.f, 0.f);

    auto step = [&](int s, int rd) {
        const int wrs = 1 - rd;
        // prefetch u for step s+3
        __half u_n3 = __float2half_rn(0.f);
        if (s + 3 < Tlen) u_n3 = up[(size_t)(s + 3) * 512];

        // GEMV over own k-half (8 broadcast LDS.128, 32 HFMA2)
        const uint4* hp = reinterpret_cast<const uint4*>(&hbuf[rd][khalf * 64]);
        __half2 a0 = z2, a1 = z2, a2 = z2, a3 = z2;
#pragma unroll
        for (int kk = 0; kk < 8; kk++) {
            union { uint4 v; __half2 h2[4]; } hv;
            hv.v = hp[kk];
            a0 = __hfma2(wr[kk * 4 + 0], hv.h2[0], a0);
            a1 = __hfma2(wr[kk * 4 + 1], hv.h2[1], a1);
            a2 = __hfma2(wr[kk * 4 + 2], hv.h2[2], a2);
            a3 = __hfma2(wr[kk * 4 + 3], hv.h2[3], a3);
        }
        __half2 b0 = __hadd2(a0, a1);
        __half2 b1 = __hadd2(a2, a3);
        float2 f0 = __half22float2(b0);
        float2 f1 = __half22float2(b1);
        float part = (f0.x + f0.y) + (f1.x + f1.y);
        float zo   = __shfl_xor_sync(FULL, part, 16);
        float z    = u_cur + part + zo;

        u_cur = __half2float(u_n1);
        u_n1  = u_n2;
        u_n2  = u_n3;

        float gv = fmaf(mm, tanhfast(sc * z), aa);

        float f_ = __shfl_sync(FULL, gv, qbase + 0);
        float i_ = __shfl_sync(FULL, gv, qbase + 1);
        float g_ = __shfl_sync(FULL, gv, qbase + 2);
        float o_ = __shfl_sync(FULL, gv, qbase + 3);

        c = fmaf(c, f_, i_ * g_);
        float hn = tanhfast(c) * o_;

        if (writer) {
            __half h16 = __float2half_rn(hn);
            hbuf[wrs][j] = h16;                                    // local
            unsigned short hv16 = __half_as_ushort(h16);
            asm volatile("st.shared::cluster.u16 [%0], %1;"
                         :: "r"(peer_hbuf + (uint32_t)(wrs * 256 + j * 2)), "h"(hv16)
                         : "memory");
            if (s == Tlen - 1) {                                   // assemble on rank 0
                if (rank == 0) hfin[j] = hn;
                else asm volatile("st.shared::cluster.u32 [%0], %1;"
                                  :: "r"(peer_hfin + (uint32_t)(j * 4)),
                                     "r"(__float_as_uint(hn)) : "memory");
            }
        }
        __syncthreads();
        if (t == 0) {
            asm volatile("fence.acq_rel.cluster;" ::: "memory");
            asm volatile("st.relaxed.cluster.shared::cluster.u32 [%0], %1;"
                         :: "r"(peer_flag), "r"((unsigned)(s + 1)) : "memory");
        }
        // relaxed poll own flag, then acquire fence
        unsigned v;
        do {
            asm volatile("ld.relaxed.cluster.shared.u32 %0, [%1];"
                         : "=r"(v) : "r"(my_flag) : "memory");
        } while (v < (unsigned)(s + 1));
        asm volatile("fence.acq_rel.cluster;" ::: "memory");
    };

#pragma unroll 1
    for (int s = 0; s < Tlen; s += 2) {
        step(s, 0);
        step(s + 1, 1);
    }

    // final head on rank 0: out[b] = sigmoid(h_T @ W_out + b_out)
    if (rank == 0) {
        if (t < Hdim) hfin[t] = hfin[t] * W_out[t];
        __syncthreads();
        if (t == 0) {
            float sacc = b_out[0];
#pragma unroll 1
            for (int k = 0; k < Hdim; k++) sacc += hfin[k];
            out[b] = fsigmoid(sacc);
        }
    }
    // keep both CTAs alive until all remote traffic settles
    asm volatile("barrier.cluster.arrive.aligned;" ::: "memory");
    asm volatile("barrier.cluster.wait.aligned;"   ::: "memory");
}

// ---------------------------------------------------------------------------
// Launch
// inputs: 0:x 1:W_emb 2:b_emb 3:W_f 4:b_f 5:W_i 6:b_i 7:W_c 8:b_c
//         9:W_o 10:b_o 11:W_out 12:b_out
// ---------------------------------------------------------------------------
extern "C" void kernel_launch(void* const* d_in, const int* in_sizes, int n_in,
                              void* d_out, int out_size)
{
    const float* x     = (const float*)d_in[0];
    const float* W_emb = (const float*)d_in[1];
    const float* b_emb = (const float*)d_in[2];
    const float* W_f   = (const float*)d_in[3];
    const float* b_f   = (const float*)d_in[4];
    const float* W_i   = (const float*)d_in[5];
    const float* b_i   = (const float*)d_in[6];
    const float* W_c   = (const float*)d_in[7];
    const float* b_c   = (const float*)d_in[8];
    const float* W_o   = (const float*)d_in[9];
    const float* b_o   = (const float*)d_in[10];
    const float* W_out = (const float*)d_in[11];
    const float* b_out = (const float*)d_in[12];
    float* out = (float*)d_out;

    const int rows = Bsz * Tlen;                      // 262144

    emb_kernel<<<rows / 256, 256>>>(x, W_emb, b_emb);
    ugemm_kernel<<<rows / 32, 256>>>(W_f, b_f, W_i, b_i, W_c, b_c, W_o, b_o);
    scan_kernel<<<Bsz * 2, 512>>>(W_f, W_i, W_c, W_o, W_out, b_out, out);
}

// round 13
// speedup vs baseline: 1.7327x; 1.7327x over previous
#include <cuda_runtime.h>
#include <cuda_fp16.h>
#include <cstdint>
#include <cstddef>

#define Bsz  64
#define Tlen 4096
#define DIN  64
#define DEMB 24
#define Hdim 128

// Scratch (static device globals — no allocation in kernel_launch)
__device__ float  g_e[(size_t)Bsz * Tlen * DEMB];              // 25 MB
__device__ __half g_u16[(size_t)Bsz * Tlen * 4 * Hdim];        // 256 MB, layout [row][j*4+gate]

__device__ __forceinline__ float tanhfast(float x) {
    float y;
    asm("tanh.approx.f32 %0, %1;" : "=f"(y) : "f"(x));
    return y;
}
__device__ __forceinline__ float fsigmoid(float z) {
    return fmaf(0.5f, tanhfast(0.5f * z), 0.5f);
}

// ---------------------------------------------------------------------------
// K1: e[r][j] = sigmoid(x[r,:] @ W_emb[:,j] + b_emb[j])   (unchanged)
// ---------------------------------------------------------------------------
__global__ void __launch_bounds__(256) emb_kernel(
    const float* __restrict__ x,
    const float* __restrict__ W_emb,
    const float* __restrict__ b_emb)
{
    __shared__ float ws[DIN * DEMB];
    __shared__ float bs[DEMB];
    for (int i = threadIdx.x; i < DIN * DEMB; i += 256) ws[i] = W_emb[i];
    if (threadIdx.x < DEMB) bs[threadIdx.x] = b_emb[threadIdx.x];
    __syncthreads();

    size_t r = (size_t)blockIdx.x * 256 + threadIdx.x;
    const float* xr = x + r * DIN;

    float acc[DEMB];
#pragma unroll
    for (int j = 0; j < DEMB; j++) acc[j] = bs[j];

#pragma unroll 1
    for (int d4 = 0; d4 < DIN; d4 += 4) {
        float4 xq = *reinterpret_cast<const float4*>(xr + d4);
        float xa[4] = { xq.x, xq.y, xq.z, xq.w };
#pragma unroll
        for (int q = 0; q < 4; q++) {
            const float4* wp = reinterpret_cast<const float4*>(ws + (d4 + q) * DEMB);
#pragma unroll
            for (int m = 0; m < 6; m++) {
                float4 wv = wp[m];
                acc[m * 4 + 0] = fmaf(xa[q], wv.x, acc[m * 4 + 0]);
                acc[m * 4 + 1] = fmaf(xa[q], wv.y, acc[m * 4 + 1]);
                acc[m * 4 + 2] = fmaf(xa[q], wv.z, acc[m * 4 + 2]);
                acc[m * 4 + 3] = fmaf(xa[q], wv.w, acc[m * 4 + 3]);
            }
        }
    }

    float* er = g_e + r * DEMB;
#pragma unroll
    for (int j = 0; j < DEMB; j++) er[j] = fsigmoid(acc[j]);
}

// ---------------------------------------------------------------------------
// K2: u[r][j*4+g] = e[r,:] @ Wg[0:24, j] + bg[j]  (fp16 out)  (unchanged)
// ---------------------------------------------------------------------------
__global__ void __launch_bounds__(256) ugemm_kernel(
    const float* __restrict__ Wf, const float* __restrict__ bf,
    const float* __restrict__ Wi, const float* __restrict__ bi,
    const float* __restrict__ Wc, const float* __restrict__ bc,
    const float* __restrict__ Wo, const float* __restrict__ bo)
{
    __shared__ float es[32][DEMB];
    size_t r0 = (size_t)blockIdx.x * 32;
    for (int i = threadIdx.x; i < 32 * DEMB; i += 256)
        es[i / DEMB][i % DEMB] = g_e[r0 * DEMB + i];
    __syncthreads();

    int tid = threadIdx.x;
    int j   = tid & 127;

    float wreg[4][DEMB];
#pragma unroll
    for (int d = 0; d < DEMB; d++) {
        wreg[0][d] = Wf[d * Hdim + j];
        wreg[1][d] = Wi[d * Hdim + j];
        wreg[2][d] = Wc[d * Hdim + j];
        wreg[3][d] = Wo[d * Hdim + j];
    }
    float bias[4] = { bf[j], bi[j], bc[j], bo[j] };

    int rbase = (tid >> 7) * 16;
#pragma unroll 1
    for (int rr = 0; rr < 16; rr++) {
        int row = rbase + rr;
        float a0 = bias[0], a1 = bias[1], a2 = bias[2], a3 = bias[3];
#pragma unroll
        for (int d = 0; d < DEMB; d++) {
            float ev = es[row][d];
            a0 = fmaf(ev, wreg[0][d], a0);
            a1 = fmaf(ev, wreg[1][d], a1);
            a2 = fmaf(ev, wreg[2][d], a2);
            a3 = fmaf(ev, wreg[3][d], a3);
        }
        __half2 lo = __floats2half2_rn(a0, a1);
        __half2 hi = __floats2half2_rn(a2, a3);
        uint2 v;
        v.x = *reinterpret_cast<uint32_t*>(&lo);
        v.y = *reinterpret_cast<uint32_t*>(&hi);
        *reinterpret_cast<uint2*>(g_u16 + ((r0 + row) * 512 + j * 4)) = v;
    }
}

// ---------------------------------------------------------------------------
// K3: sequential scan. 64 CTAs (one per batch), 256 threads.
//     Thread t owns unit j = t>>1, gate-pair gp = t&1 (gp0:{f,i}, gp1:{c,o}).
//     u half2 index within a row: 2j+gp == t (FIXED: was 2t in R12 -> OOB).
//     Per thread: 128 HFMA2 (2 gates x 64), 16 broadcast LDS.128, 2 SHFLs,
//     3 MUFU.TANH. Gate exchange via shfl_xor(1); one __syncthreads per step.
//     Recurrent weights: 128 half2 registers per thread (~160 regs total).
// ---------------------------------------------------------------------------
__global__ void __launch_bounds__(256, 1) scan_kernel(
    const float* __restrict__ Wf, const float* __restrict__ Wi,
    const float* __restrict__ Wc, const float* __restrict__ Wo,
    const float* __restrict__ W_out, const float* __restrict__ b_out,
    float* __restrict__ out)
{
    const int b  = blockIdx.x;
    const int t  = threadIdx.x;          // 0..255
    const int j  = t >> 1;               // hidden unit 0..127
    const int gp = t & 1;                // 0:{f,i}  1:{c,o}
    const unsigned FULL = 0xFFFFFFFFu;

    const float* WgA = gp ? Wc : Wf;     // slot 0: f or c
    const float* WgB = gp ? Wo : Wi;     // slot 1: i or o

    // Recurrent weights (rows 24..151, column j) for both gates, half2-packed
    __half2 wA[64], wB[64];
#pragma unroll
    for (int k = 0; k < 64; k++) {
        int row = DEMB + 2 * k;
        wA[k] = __floats2half2_rn(WgA[row * Hdim + j], WgA[(row + 1) * Hdim + j]);
        wB[k] = __floats2half2_rn(WgB[row * Hdim + j], WgB[(row + 1) * Hdim + j]);
    }

    // slot-0 activation: gp0 -> sigmoid(f), gp1 -> tanh(g); slot 1 always sigmoid
    const float scA = gp ? 1.f : 0.5f;
    const float mmA = gp ? 1.f : 0.5f;
    const float aaA = gp ? 0.f : 0.5f;

    __shared__ __align__(16) __half hbuf[2][Hdim];
    __shared__ float hfin[Hdim];

    if (t < Hdim) hbuf[0][t] = __float2half_rn(0.f);
    float c = 0.f, hkeep = 0.f;

    // u: this thread's two gate halves are half2 index t within the row;
    // row stride = 256 half2.
    const __half2* up2 = reinterpret_cast<const __half2*>(
        g_u16 + ((size_t)b * Tlen) * 512) + t;
    float2  u_cur = __half22float2(up2[0]);
    __half2 u_n1  = up2[256];
    __half2 u_n2  = up2[512];
    __syncthreads();

    const __half2 z2 = __floats2half2_rn(0.f, 0.f);

    auto step = [&](int s, int rd) {
        const int wrs = 1 - rd;
        // prefetch u for step s+3 (consumed ~2.5 steps later)
        __half2 u_n3 = z2;
        if (s + 3 < Tlen) u_n3 = up2[(size_t)(s + 3) * 256];

        // dual GEMV over h (16 broadcast LDS.128, 128 HFMA2)
        const uint4* hp = reinterpret_cast<const uint4*>(hbuf[rd]);
        __half2 aA0 = z2, aA1 = z2, aA2 = z2, aA3 = z2;
        __half2 aB0 = z2, aB1 = z2, aB2 = z2, aB3 = z2;
#pragma unroll
        for (int kk = 0; kk < 16; kk++) {
            union { uint4 v; __half2 h2[4]; } hv;
            hv.v = hp[kk];
            aA0 = __hfma2(wA[kk * 4 + 0], hv.h2[0], aA0);
            aA1 = __hfma2(wA[kk * 4 + 1], hv.h2[1], aA1);
            aA2 = __hfma2(wA[kk * 4 + 2], hv.h2[2], aA2);
            aA3 = __hfma2(wA[kk * 4 + 3], hv.h2[3], aA3);
            aB0 = __hfma2(wB[kk * 4 + 0], hv.h2[0], aB0);
            aB1 = __hfma2(wB[kk * 4 + 1], hv.h2[1], aB1);
            aB2 = __hfma2(wB[kk * 4 + 2], hv.h2[2], aB2);
            aB3 = __hfma2(wB[kk * 4 + 3], hv.h2[3], aB3);
        }
        __half2 rA = __hadd2(__hadd2(aA0, aA1), __hadd2(aA2, aA3));
        __half2 rB = __hadd2(__hadd2(aB0, aB1), __hadd2(aB2, aB3));
        float2 fA = __half22float2(rA);
        float2 fB = __half22float2(rB);
        float zA = u_cur.x + (fA.x + fA.y);
        float zB = u_cur.y + (fB.x + fB.y);

        // shift u pipeline
        u_cur = __half22float2(u_n1);
        u_n1  = u_n2;
        u_n2  = u_n3;

        // activations
        float gvA = fmaf(mmA, tanhfast(scA * zA), aaA);   // f (gp0) or g (gp1)
        float gvB = fsigmoid(zB);                          // i (gp0) or o (gp1)

        // exchange with partner lane (unit's other gate pair)
        float oA = __shfl_xor_sync(FULL, gvA, 1);
        float oB = __shfl_xor_sync(FULL, gvB, 1);

        float f_ = gp ? oA  : gvA;
        float i_ = gp ? oB  : gvB;
        float g_ = gp ? gvA : oA;
        float o_ = gp ? gvB : oB;

        // redundant cell update (identical in both lanes of the pair)
        c = fmaf(c, f_, i_ * g_);
        float hn = tanhfast(c) * o_;
        hkeep = hn;
        if (gp == 0) hbuf[wrs][j] = __float2half_rn(hn);
        __syncthreads();   // single barrier per step
    };

#pragma unroll 1
    for (int s = 0; s < Tlen; s += 2) {
        step(s, 0);
        step(s + 1, 1);
    }

    // final head: out[b] = sigmoid(h_T @ W_out + b_out)
    if (gp == 0) hfin[j] = hkeep * W_out[j];
    __syncthreads();
    if (t == 0) {
        float sacc = b_out[0];
#pragma unroll 1
        for (int k = 0; k < Hdim; k++) sacc += hfin[k];
        out[b] = fsigmoid(sacc);
    }
}

// ---------------------------------------------------------------------------
// Launch
// inputs: 0:x 1:W_emb 2:b_emb 3:W_f 4:b_f 5:W_i 6:b_i 7:W_c 8:b_c
//         9:W_o 10:b_o 11:W_out 12:b_out
// ---------------------------------------------------------------------------
extern "C" void kernel_launch(void* const* d_in, const int* in_sizes, int n_in,
                              void* d_out, int out_size)
{
    const float* x     = (const float*)d_in[0];
    const float* W_emb = (const float*)d_in[1];
    const float* b_emb = (const float*)d_in[2];
    const float* W_f   = (const float*)d_in[3];
    const float* b_f   = (const float*)d_in[4];
    const float* W_i   = (const float*)d_in[5];
    const float* b_i   = (const float*)d_in[6];
    const float* W_c   = (const float*)d_in[7];
    const float* b_c   = (const float*)d_in[8];
    const float* W_o   = (const float*)d_in[9];
    const float* b_o   = (const float*)d_in[10];
    const float* W_out = (const float*)d_in[11];
    const float* b_out = (const float*)d_in[12];
    float* out = (float*)d_out;

    const int rows = Bsz * Tlen;                      // 262144

    emb_kernel<<<rows / 256, 256>>>(x, W_emb, b_emb);
    ugemm_kernel<<<rows / 32, 256>>>(W_f, b_f, W_i, b_i, W_c, b_c, W_o, b_o);
    scan_kernel<<<Bsz, 256>>>(W_f, W_i, W_c, W_o, W_out, b_out, out);
}

// round 14
// speedup vs baseline: 1.9265x; 1.1119x over previous
#include <cuda_runtime.h>
#include <cuda_fp16.h>
#include <cstdint>
#include <cstddef>

#define Bsz  64
#define Tlen 4096
#define DIN  64
#define DEMB 24
#define Hdim 128

// Scratch (static device globals — no allocation in kernel_launch)
__device__ __half g_u16[(size_t)Bsz * Tlen * 4 * Hdim];   // 256 MB, layout [row][j*4+gate]
__device__ int    g_done[Bsz];                            // per-batch chunk ticket (zero-init; reset by scan)

__device__ __forceinline__ float tanhfast(float x) {
    float y;
    asm("tanh.approx.f32 %0, %1;" : "=f"(y) : "f"(x));
    return y;
}
__device__ __forceinline__ float fsigmoid(float z) {
    return fmaf(0.5f, tanhfast(0.5f * z), 0.5f);
}

// ---------------------------------------------------------------------------
// Fused kernel.
//  blocks [0,64):       scan, one batch each (exclusive SM via launch_bounds 1)
//  blocks [64, 64+8192): producer p = blk-64: batch b = p&63, chunk k = p>>6
//                        (k-major => early timesteps produced first; ticket
//                        chain makes done[b]*32 a prefix-complete row count)
// ---------------------------------------------------------------------------
__global__ void __launch_bounds__(256, 1) fused_kernel(
    const float* __restrict__ x,
    const float* __restrict__ W_emb, const float* __restrict__ b_emb,
    const float* __restrict__ Wf, const float* __restrict__ bf,
    const float* __restrict__ Wi, const float* __restrict__ bi,
    const float* __restrict__ Wc, const float* __restrict__ bc,
    const float* __restrict__ Wo, const float* __restrict__ bo,
    const float* __restrict__ W_out, const float* __restrict__ b_out,
    float* __restrict__ out)
{
    const int tid = threadIdx.x;

    if (blockIdx.x >= 64) {
        // =================== PRODUCER ===================
        const int p  = blockIdx.x - 64;
        const int b  = p & 63;
        const int k  = p >> 6;              // chunk 0..127
        const size_t r0 = (size_t)b * Tlen + (size_t)k * 32;   // first global row

        __shared__ float xs[32][DIN];       // 8 KB
        __shared__ float ws[DIN * DEMB];    // 6 KB
        __shared__ float bs[DEMB];
        __shared__ float es[32][DEMB];      // 3 KB

        // coop loads
        {
            const float4* xsrc = reinterpret_cast<const float4*>(x + r0 * DIN);
            float4* xdst = reinterpret_cast<float4*>(&xs[0][0]);
#pragma unroll
            for (int i = 0; i < 2; i++) xdst[tid + 256 * i] = xsrc[tid + 256 * i];
            for (int i = tid; i < DIN * DEMB; i += 256) ws[i] = W_emb[i];
            if (tid < DEMB) bs[tid] = b_emb[tid];
        }
        __syncthreads();

        // e = sigmoid(x @ W_emb + b): thread -> (row = tid>>3, 3 outputs)
        {
            const int r  = tid >> 3;
            const int j0 = (tid & 7) * 3;
            float a0 = bs[j0], a1 = bs[j0 + 1], a2 = bs[j0 + 2];
#pragma unroll
            for (int d = 0; d < DIN; d++) {
                float xv = xs[r][d];
                a0 = fmaf(xv, ws[d * DEMB + j0    ], a0);
                a1 = fmaf(xv, ws[d * DEMB + j0 + 1], a1);
                a2 = fmaf(xv, ws[d * DEMB + j0 + 2], a2);
            }
            es[r][j0]     = fsigmoid(a0);
            es[r][j0 + 1] = fsigmoid(a1);
            es[r][j0 + 2] = fsigmoid(a2);
        }
        __syncthreads();

        // u[r][j*4+g] = e[r,:] @ Wg[0:24, j] + bg[j]  (fp16)
        {
            const int j = tid & 127;
            float wreg[4][DEMB];
#pragma unroll
            for (int d = 0; d < DEMB; d++) {
                wreg[0][d] = Wf[d * Hdim + j];
                wreg[1][d] = Wi[d * Hdim + j];
                wreg[2][d] = Wc[d * Hdim + j];
                wreg[3][d] = Wo[d * Hdim + j];
            }
            float bias[4] = { bf[j], bi[j], bc[j], bo[j] };

            const int rbase = (tid >> 7) * 16;
#pragma unroll 1
            for (int rr = 0; rr < 16; rr++) {
                int row = rbase + rr;
                float a0 = bias[0], a1 = bias[1], a2 = bias[2], a3 = bias[3];
#pragma unroll
                for (int d = 0; d < DEMB; d++) {
                    float ev = es[row][d];
                    a0 = fmaf(ev, wreg[0][d], a0);
                    a1 = fmaf(ev, wreg[1][d], a1);
                    a2 = fmaf(ev, wreg[2][d], a2);
                    a3 = fmaf(ev, wreg[3][d], a3);
                }
                __half2 lo = __floats2half2_rn(a0, a1);
                __half2 hi = __floats2half2_rn(a2, a3);
                uint2 v;
                v.x = *reinterpret_cast<uint32_t*>(&lo);
                v.y = *reinterpret_cast<uint32_t*>(&hi);
                *reinterpret_cast<uint2*>(g_u16 + ((r0 + row) * 512 + j * 4)) = v;
            }
        }

        __syncthreads();
        __threadfence();
        if (tid == 0) {
            volatile int* dn = g_done + b;
            while (*dn != k) { }            // predecessors have lower blockIdx
            *dn = k + 1;                    // publish prefix
        }
        return;
    }

    // ===================== SCAN =====================
    const int b  = blockIdx.x;
    const int t  = tid;                  // 0..255
    const int j  = t >> 1;               // hidden unit 0..127
    const int gp = t & 1;                // 0:{f,i}  1:{c,o}
    const unsigned FULL = 0xFFFFFFFFu;

    const float* WgA = gp ? Wc : Wf;     // slot 0: f or c
    const float* WgB = gp ? Wo : Wi;     // slot 1: i or o

    // Recurrent weights (rows 24..151, column j) for both gates, half2-packed
    __half2 wA[64], wB[64];
#pragma unroll
    for (int k = 0; k < 64; k++) {
        int row = DEMB + 2 * k;
        wA[k] = __floats2half2_rn(WgA[row * Hdim + j], WgA[(row + 1) * Hdim + j]);
        wB[k] = __floats2half2_rn(WgB[row * Hdim + j], WgB[(row + 1) * Hdim + j]);
    }

    // slot-0 activation: gp0 -> sigmoid(f), gp1 -> tanh(g); slot 1 always sigmoid
    const float scA = gp ? 1.f : 0.5f;
    const float mmA = gp ? 1.f : 0.5f;
    const float aaA = gp ? 0.f : 0.5f;

    __shared__ __align__(16) __half hbuf[2][Hdim];
    __shared__ float hfin[Hdim];

    if (t < Hdim) hbuf[0][t] = __float2half_rn(0.f);
    float c = 0.f, hkeep = 0.f;

    volatile int* dn = g_done + b;
    int ready = 0;                        // rows known complete = done[b]*32
    while (ready < 3) ready = (*dn) << 5; // need rows 0..2 for the initial loads
    __threadfence();

    // u: this thread's two gate halves are half2 index t within the row
    const __half2* up2 = reinterpret_cast<const __half2*>(
        g_u16 + ((size_t)b * Tlen) * 512) + t;
    float2  u_cur = __half22float2(up2[0]);
    __half2 u_n1  = up2[256];
    __half2 u_n2  = up2[512];
    __syncthreads();

    const __half2 z2 = __floats2half2_rn(0.f, 0.f);

    auto step = [&](int s, int rd) {
        const int wrs = 1 - rd;
        // prefetch u for step s+3 (consumed ~2.5 steps later)
        __half2 u_n3 = z2;
        if (s + 3 < Tlen) u_n3 = up2[(size_t)(s + 3) * 256];

        // dual GEMV over h (16 broadcast LDS.128, 128 HFMA2)
        const uint4* hp = reinterpret_cast<const uint4*>(hbuf[rd]);
        __half2 aA0 = z2, aA1 = z2, aA2 = z2, aA3 = z2;
        __half2 aB0 = z2, aB1 = z2, aB2 = z2, aB3 = z2;
#pragma unroll
        for (int kk = 0; kk < 16; kk++) {
            union { uint4 v; __half2 h2[4]; } hv;
            hv.v = hp[kk];
            aA0 = __hfma2(wA[kk * 4 + 0], hv.h2[0], aA0);
            aA1 = __hfma2(wA[kk * 4 + 1], hv.h2[1], aA1);
            aA2 = __hfma2(wA[kk * 4 + 2], hv.h2[2], aA2);
            aA3 = __hfma2(wA[kk * 4 + 3], hv.h2[3], aA3);
            aB0 = __hfma2(wB[kk * 4 + 0], hv.h2[0], aB0);
            aB1 = __hfma2(wB[kk * 4 + 1], hv.h2[1], aB1);
            aB2 = __hfma2(wB[kk * 4 + 2], hv.h2[2], aB2);
            aB3 = __hfma2(wB[kk * 4 + 3], hv.h2[3], aB3);
        }
        __half2 rA = __hadd2(__hadd2(aA0, aA1), __hadd2(aA2, aA3));
        __half2 rB = __hadd2(__hadd2(aB0, aB1), __hadd2(aB2, aB3));
        float2 fA = __half22float2(rA);
        float2 fB = __half22float2(rB);
        float zA = u_cur.x + (fA.x + fA.y);
        float zB = u_cur.y + (fB.x + fB.y);

        // shift u pipeline
        u_cur = __half22float2(u_n1);
        u_n1  = u_n2;
        u_n2  = u_n3;

        // activations
        float gvA = fmaf(mmA, tanhfast(scA * zA), aaA);   // f (gp0) or g (gp1)
        float gvB = fsigmoid(zB);                          // i (gp0) or o (gp1)

        // exchange with partner lane (unit's other gate pair)
        float oA = __shfl_xor_sync(FULL, gvA, 1);
        float oB = __shfl_xor_sync(FULL, gvB, 1);

        float f_ = gp ? oA  : gvA;
        float i_ = gp ? oB  : gvB;
        float g_ = gp ? gvA : oA;
        float o_ = gp ? gvB : oB;

        // redundant cell update (identical in both lanes of the pair)
        c = fmaf(c, f_, i_ * g_);
        float hn = tanhfast(c) * o_;
        hkeep = hn;
        if (gp == 0) hbuf[wrs][j] = __float2half_rn(hn);
        __syncthreads();   // single barrier per step
    };

#pragma unroll 1
    for (int s = 0; s < Tlen; s += 2) {
        // guard prefetches for this pair: rows s+3 and s+4 (clamped at the end)
        int need = s + 4;
        if (need > Tlen - 1) need = Tlen - 1;
        if (ready <= need) {
            do { ready = (*dn) << 5; } while (ready <= need);
            __threadfence();
        }
        step(s, 0);
        step(s + 1, 1);
    }

    // final head: out[b] = sigmoid(h_T @ W_out + b_out)
    if (gp == 0) hfin[j] = hkeep * W_out[j];
    __syncthreads();
    if (t == 0) {
        float sacc = b_out[0];
#pragma unroll 1
        for (int k = 0; k < Hdim; k++) sacc += hfin[k];
        out[b] = fsigmoid(sacc);
        *dn = 0;                          // reset ticket for next graph replay
    }
}

// ---------------------------------------------------------------------------
// Launch
// inputs: 0:x 1:W_emb 2:b_emb 3:W_f 4:b_f 5:W_i 6:b_i 7:W_c 8:b_c
//         9:W_o 10:b_o 11:W_out 12:b_out
// ---------------------------------------------------------------------------
extern "C" void kernel_launch(void* const* d_in, const int* in_sizes, int n_in,
                              void* d_out, int out_size)
{
    const float* x     = (const float*)d_in[0];
    const float* W_emb = (const float*)d_in[1];
    const float* b_emb = (const float*)d_in[2];
    const float* W_f   = (const float*)d_in[3];
    const float* b_f   = (const float*)d_in[4];
    const float* W_i   = (const float*)d_in[5];
    const float* b_i   = (const float*)d_in[6];
    const float* W_c   = (const float*)d_in[7];
    const float* b_c   = (const float*)d_in[8];
    const float* W_o   = (const float*)d_in[9];
    const float* b_o   = (const float*)d_in[10];
    const float* W_out = (const float*)d_in[11];
    const float* b_out = (const float*)d_in[12];
    float* out = (float*)d_out;

    // 64 scan blocks + 64*128 producer blocks
    fused_kernel<<<64 + Bsz * (Tlen / 32), 256>>>(
        x, W_emb, b_emb, W_f, b_f, W_i, b_i, W_c, b_c, W_o, b_o,
        W_out, b_out, out);
}

// round 16
// speedup vs baseline: 2.1427x; 1.1122x over previous
#include <cuda_runtime.h>
#include <cuda_fp16.h>
#include <cstdint>
#include <cstddef>

#define Bsz  64
#define Tlen 4096
#define DIN  64
#define DEMB 24
#define Hdim 128

// Scratch (static device globals — no allocation in kernel_launch)
__device__ __half g_u16[(size_t)Bsz * Tlen * 4 * Hdim];   // 256 MB, layout [row][j*4+gate]
__device__ int    g_done[Bsz];                            // per-batch chunk ticket (zero-init; reset by scan)

__device__ __forceinline__ float tanhfast(float x) {
    float y;
    asm("tanh.approx.f32 %0, %1;" : "=f"(y) : "f"(x));
    return y;
}
__device__ __forceinline__ float fsigmoid(float z) {
    return fmaf(0.5f, tanhfast(0.5f * z), 0.5f);
}
__device__ __forceinline__ __half2 tanh2fast(__half2 x) {
    uint32_t xi = *reinterpret_cast<uint32_t*>(&x);
    uint32_t yi;
    asm("tanh.approx.f16x2 %0, %1;" : "=r"(yi) : "r"(xi));
    return *reinterpret_cast<__half2*>(&yi);
}

// ---------------------------------------------------------------------------
// Fused kernel.
//  blocks [0,64):        scan, one batch each (exclusive SM: 255 regs/thread)
//  blocks [64, 64+8192): producer p = blk-64: batch b = p&63, chunk k = p>>6
//                        (k-major => early timesteps produced first; ticket
//                        chain makes done[b]*32 a prefix-complete row count)
// ---------------------------------------------------------------------------
__global__ void __launch_bounds__(256, 1) fused_kernel(
    const float* __restrict__ x,
    const float* __restrict__ W_emb, const float* __restrict__ b_emb,
    const float* __restrict__ Wf, const float* __restrict__ bf,
    const float* __restrict__ Wi, const float* __restrict__ bi,
    const float* __restrict__ Wc, const float* __restrict__ bc,
    const float* __restrict__ Wo, const float* __restrict__ bo,
    const float* __restrict__ W_out, const float* __restrict__ b_out,
    float* __restrict__ out)
{
    const int tid = threadIdx.x;

    if (blockIdx.x >= 64) {
        // =================== PRODUCER ===================
        const int p  = blockIdx.x - 64;
        const int b  = p & 63;
        const int k  = p >> 6;              // chunk 0..127
        const size_t r0 = (size_t)b * Tlen + (size_t)k * 32;   // first global row

        __shared__ float xs[32][DIN];       // 8 KB
        __shared__ float ws[DIN * DEMB];    // 6 KB
        __shared__ float bs[DEMB];
        __shared__ float es[32][DEMB];      // 3 KB

        {
            const float4* xsrc = reinterpret_cast<const float4*>(x + r0 * DIN);
            float4* xdst = reinterpret_cast<float4*>(&xs[0][0]);
#pragma unroll
            for (int i = 0; i < 2; i++) xdst[tid + 256 * i] = xsrc[tid + 256 * i];
            for (int i = tid; i < DIN * DEMB; i += 256) ws[i] = W_emb[i];
            if (tid < DEMB) bs[tid] = b_emb[tid];
        }
        __syncthreads();

        // e = sigmoid(x @ W_emb + b): thread -> (row = tid>>3, 3 outputs)
        {
            const int r  = tid >> 3;
            const int j0 = (tid & 7) * 3;
            float a0 = bs[j0], a1 = bs[j0 + 1], a2 = bs[j0 + 2];
#pragma unroll
            for (int d = 0; d < DIN; d++) {
                float xv = xs[r][d];
                a0 = fmaf(xv, ws[d * DEMB + j0    ], a0);
                a1 = fmaf(xv, ws[d * DEMB + j0 + 1], a1);
                a2 = fmaf(xv, ws[d * DEMB + j0 + 2], a2);
            }
            es[r][j0]     = fsigmoid(a0);
            es[r][j0 + 1] = fsigmoid(a1);
            es[r][j0 + 2] = fsigmoid(a2);
        }
        __syncthreads();

        // u[r][j*4+g] = e[r,:] @ Wg[0:24, j] + bg[j]  (fp16)
        {
            const int j = tid & 127;
            float wreg[4][DEMB];
#pragma unroll
            for (int d = 0; d < DEMB; d++) {
                wreg[0][d] = Wf[d * Hdim + j];
                wreg[1][d] = Wi[d * Hdim + j];
                wreg[2][d] = Wc[d * Hdim + j];
                wreg[3][d] = Wo[d * Hdim + j];
            }
            float bias[4] = { bf[j], bi[j], bc[j], bo[j] };

            const int rbase = (tid >> 7) * 16;
#pragma unroll 1
            for (int rr = 0; rr < 16; rr++) {
                int row = rbase + rr;
                float a0 = bias[0], a1 = bias[1], a2 = bias[2], a3 = bias[3];
#pragma unroll
                for (int d = 0; d < DEMB; d++) {
                    float ev = es[row][d];
                    a0 = fmaf(ev, wreg[0][d], a0);
                    a1 = fmaf(ev, wreg[1][d], a1);
                    a2 = fmaf(ev, wreg[2][d], a2);
                    a3 = fmaf(ev, wreg[3][d], a3);
                }
                __half2 lo = __floats2half2_rn(a0, a1);
                __half2 hi = __floats2half2_rn(a2, a3);
                uint2 v;
                v.x = *reinterpret_cast<uint32_t*>(&lo);
                v.y = *reinterpret_cast<uint32_t*>(&hi);
                *reinterpret_cast<uint2*>(g_u16 + ((r0 + row) * 512 + j * 4)) = v;
            }
        }

        __syncthreads();
        __threadfence();
        if (tid == 0) {
            volatile int* dn = g_done + b;
            while (*dn != k) { }            // predecessors have lower blockIdx
            *dn = k + 1;                    // publish prefix
        }
        return;
    }

    // ===================== SCAN =====================
    const int b  = blockIdx.x;
    const int t  = tid;                  // 0..255
    const int j  = t >> 1;               // hidden unit 0..127
    const int gp = t & 1;                // 0:{f,i}  1:{c,o}
    const unsigned FULL = 0xFFFFFFFFu;

    const float* WgA = gp ? Wc : Wf;     // slot 0: f or c
    const float* WgB = gp ? Wo : Wi;     // slot 1: i or o

    // Recurrent weights (rows 24..151, column j) for both gates, half2-packed
    __half2 wA[64], wB[64];
#pragma unroll
    for (int k = 0; k < 64; k++) {
        int row = DEMB + 2 * k;
        wA[k] = __floats2half2_rn(WgA[row * Hdim + j], WgA[(row + 1) * Hdim + j]);
        wB[k] = __floats2half2_rn(WgB[row * Hdim + j], WgB[(row + 1) * Hdim + j]);
    }

    // vector activation constants for this lane's two gates:
    //   gp0 = {f:sigmoid, i:sigmoid}  -> 0.5*tanh(0.5z)+0.5 in both halves
    //   gp1 = {g:tanh,    o:sigmoid}  -> (1*tanh(1z)+0, 0.5*tanh(0.5z)+0.5)
    const __half2 sc2 = gp ? __floats2half2_rn(1.f, 0.5f)
                           : __floats2half2_rn(0.5f, 0.5f);
    const __half2 aa2 = gp ? __floats2half2_rn(0.f, 0.5f)
                           : __floats2half2_rn(0.5f, 0.5f);

    __shared__ __align__(16) __half hbuf[2][Hdim];
    __shared__ float hfin[Hdim];

    if (t < Hdim) hbuf[0][t] = __float2half_rn(0.f);
    float c = 0.f, hkeep = 0.f;

    volatile int* dn = g_done + b;
    int ready = 0;                        // rows known complete = done[b]*32
    while (ready < 3) ready = (*dn) << 5; // rows 0..2 for the initial loads
    __threadfence();

    // u: this lane's two gate halves are half2 index t within the row;
    // row stride = 256 half2. Keep the pipeline as raw half2.
    const uint32_t* upw = reinterpret_cast<const uint32_t*>(
        g_u16 + ((size_t)b * Tlen) * 512) + t;
    uint32_t u_cur = upw[0];
    uint32_t u_n1  = upw[256];
    uint32_t u_n2  = upw[512];
    __syncthreads();

    const __half2 z2 = __floats2half2_rn(0.f, 0.f);

    auto step = [&](int s, int rd) {
        const int wrs = 1 - rd;
        // prefetch u for step s+3 (consumed ~2.5 steps later)
        uint32_t u_n3 = 0u;
        if (s + 3 < Tlen) u_n3 = upw[(size_t)(s + 3) * 256];

        // dual GEMV over h (16 broadcast LDS.128, 128 HFMA2)
        const uint4* hp = reinterpret_cast<const uint4*>(hbuf[rd]);
        __half2 aA0 = z2, aA1 = z2, aA2 = z2, aA3 = z2;
        __half2 aB0 = z2, aB1 = z2, aB2 = z2, aB3 = z2;
#pragma unroll
        for (int kk = 0; kk < 16; kk++) {
            union { uint4 v; __half2 h2[4]; } hv;
            hv.v = hp[kk];
            aA0 = __hfma2(wA[kk * 4 + 0], hv.h2[0], aA0);
            aA1 = __hfma2(wA[kk * 4 + 1], hv.h2[1], aA1);
            aA2 = __hfma2(wA[kk * 4 + 2], hv.h2[2], aA2);
            aA3 = __hfma2(wA[kk * 4 + 3], hv.h2[3], aA3);
            aB0 = __hfma2(wB[kk * 4 + 0], hv.h2[0], aB0);
            aB1 = __hfma2(wB[kk * 4 + 1], hv.h2[1], aB1);
            aB2 = __hfma2(wB[kk * 4 + 2], hv.h2[2], aB2);
            aB3 = __hfma2(wB[kk * 4 + 3], hv.h2[3], aB3);
        }
        __half2 rA = __hadd2(__hadd2(aA0, aA1), __hadd2(aA2, aA3));
        __half2 rB = __hadd2(__hadd2(aB0, aB1), __hadd2(aB2, aB3));

        // z for both gates as one half2: (sumA, sumB) + (uA, uB)
        __half2 lows  = __lows2half2(rA, rB);
        __half2 highs = __highs2half2(rA, rB);
        __half2 zh2   = __hadd2(__hadd2(lows, highs),
                                *reinterpret_cast<__half2*>(&u_cur));

        // shift u pipeline
        u_cur = u_n1; u_n1 = u_n2; u_n2 = u_n3;

        // vector activation: one tanh.approx.f16x2 covers both gates
        __half2 gv2 = __hfma2(sc2, tanh2fast(__hmul2(sc2, zh2)), aa2);

        // single packed exchange with partner lane
        uint32_t gvbits = *reinterpret_cast<uint32_t*>(&gv2);
        uint32_t ogbits = __shfl_xor_sync(FULL, gvbits, 1);
        __half2 og2 = *reinterpret_cast<__half2*>(&ogbits);

        __half2 fi2 = gp ? og2 : gv2;     // (f, i)
        __half2 go2 = gp ? gv2 : og2;     // (g, o)
        float2 fi = __half22float2(fi2);
        float2 go = __half22float2(go2);

        // redundant cell update (identical in both lanes of the pair)
        c = fmaf(c, fi.x, fi.y * go.x);
        float hn = tanhfast(c) * go.y;
        if (gp == 0) hbuf[wrs][j] = __float2half_rn(hn);
        hkeep = hn;
        __syncthreads();   // single barrier per step
    };

#pragma unroll 1
    for (int s = 0; s < Tlen; s += 2) {
        // guard prefetches for this pair: rows s+3 and s+4 (clamped at the end)
        int need = s + 4;
        if (need > Tlen - 1) need = Tlen - 1;
        if (ready <= need) {
            do { ready = (*dn) << 5; } while (ready <= need);
            __threadfence();
        }
        step(s, 0);
        step(s + 1, 1);
    }

    // final head: out[b] = sigmoid(h_T @ W_out + b_out)
    if (gp == 0) hfin[j] = hkeep * W_out[j];
    __syncthreads();
    if (t == 0) {
        float sacc = b_out[0];
#pragma unroll 1
        for (int k = 0; k < Hdim; k++) sacc += hfin[k];
        out[b] = fsigmoid(sacc);
        *dn = 0;                          // reset ticket for next graph replay
    }
}

// ---------------------------------------------------------------------------
// Launch
// inputs: 0:x 1:W_emb 2:b_emb 3:W_f 4:b_f 5:W_i 6:b_i 7:W_c 8:b_c
//         9:W_o 10:b_o 11:W_out 12:b_out
// ---------------------------------------------------------------------------
extern "C" void kernel_launch(void* const* d_in, const int* in_sizes, int n_in,
                              void* d_out, int out_size)
{
    const float* x     = (const float*)d_in[0];
    const float* W_emb = (const float*)d_in[1];
    const float* b_emb = (const float*)d_in[2];
    const float* W_f   = (const float*)d_in[3];
    const float* b_f   = (const float*)d_in[4];
    const float* W_i   = (const float*)d_in[5];
    const float* b_i   = (const float*)d_in[6];
    const float* W_c   = (const float*)d_in[7];
    const float* b_c   = (const float*)d_in[8];
    const float* W_o   = (const float*)d_in[9];
    const float* b_o   = (const float*)d_in[10];
    const float* W_out = (const float*)d_in[11];
    const float* b_out = (const float*)d_in[12];
    float* out = (float*)d_out;

    // 64 scan blocks + 64*128 producer blocks
    fused_kernel<<<64 + Bsz * (Tlen / 32), 256>>>(
        x, W_emb, b_emb, W_f, b_f, W_i, b_i, W_c, b_c, W_o, b_o,
        W_out, b_out, out);
}